// round 5
// baseline (speedup 1.0000x reference)
#include <cuda_runtime.h>
#include <cstdint>

#define DINL __device__ __forceinline__

// ---------------- problem constants ----------------
static constexpr int L   = 128;  // rows per operand tile (M and N)
static constexpr int D   = 768;  // reduction dim
static constexpr int KC  = 48;   // fp32 elements per K-chunk
static constexpr int NCH = D / KC;  // 16 chunks
static constexpr int NKS = KC / 8;  // 6 k-steps of 8 per chunk
static constexpr int STAGES = 2;

// smem: padded row stride of 52 floats -> conflict-free LDS and STS patterns
static constexpr int RS = 52;                         // row stride in floats
static constexpr int TILE_FLOATS  = L * RS;           // 6656 floats = 26 KB
static constexpr int STAGE_FLOATS = 2 * TILE_FLOATS;  // A + B = 52 KB
static constexpr int HDR_FLOATS   = 272;              // rowmax[256] + wsum[8] + pad
static constexpr uint32_t TILE_BYTES  = TILE_FLOATS * 4;   // 26624
static constexpr uint32_t STAGE_BYTES = STAGE_FLOATS * 4;  // 53248
static constexpr uint32_t SMEM_DYN =
    (HDR_FLOATS + STAGES * STAGE_FLOATS) * sizeof(float);  // 107,584 B

// ---------------- PTX helpers ----------------
DINL uint32_t smem_u32(const void* p) {
    uint32_t a;
    asm("{ .reg .u64 t; cvta.to.shared.u64 t, %1; cvt.u32.u64 %0, t; }" : "=r"(a) : "l"(p));
    return a;
}
DINL void cp_async16(uint32_t dst, const void* src) {
    asm volatile("cp.async.cg.shared.global [%0], [%1], 16;" :: "r"(dst), "l"(src) : "memory");
}
DINL void cp_commit() { asm volatile("cp.async.commit_group;" ::: "memory"); }
DINL void cp_wait0()  { asm volatile("cp.async.wait_group 0;" ::: "memory"); }

DINL void mma_tf32(float* d, const uint32_t* a, const uint32_t* b) {
    asm volatile(
        "mma.sync.aligned.m16n8k8.row.col.f32.tf32.tf32.f32 "
        "{%0,%1,%2,%3}, {%4,%5,%6,%7}, {%8,%9}, {%0,%1,%2,%3};\n"
        : "+f"(d[0]), "+f"(d[1]), "+f"(d[2]), "+f"(d[3])
        : "r"(a[0]), "r"(a[1]), "r"(a[2]), "r"(a[3]), "r"(b[0]), "r"(b[1]));
}

DINL uint32_t f2u(float x) { return __float_as_uint(x); }

// A fragment for this warp's two 16-row m-tiles at k-offset k0.
// pA points at sA + (wr*32+qid)*RS + qlan.
DINL void load_a(uint32_t (&a)[2][4], const float* __restrict__ pA, int k0) {
#pragma unroll
    for (int mt = 0; mt < 2; mt++) {
        const int base = mt * 16 * RS;
        a[mt][0] = f2u(pA[base + k0]);
        a[mt][1] = f2u(pA[base + 8 * RS + k0]);
        a[mt][2] = f2u(pA[base + k0 + 4]);
        a[mt][3] = f2u(pA[base + 8 * RS + k0 + 4]);
    }
}
// B fragments for this warp's eight 8-col n-tiles at k-offset k0.
// pB points at sB + (wc*64+qid)*RS + qlan.
DINL void load_b(uint32_t (&b)[8][2], const float* __restrict__ pB, int k0) {
#pragma unroll
    for (int nt = 0; nt < 8; nt++) {
        b[nt][0] = f2u(pB[nt * 8 * RS + k0]);
        b[nt][1] = f2u(pB[nt * 8 * RS + k0 + 4]);
    }
}

// ---------------- kernel ----------------
// One CTA per (b,k) pair. sim = ctx @ ent^T via tf32 mma.sync in registers;
// out[pair] = sum over rows of rowwise max of sim.
__global__ void __launch_bounds__(256, 2)
som_kernel(const float* __restrict__ in, float* __restrict__ out) {
    extern __shared__ float smem[];
    float* rowbuf = smem;            // [2][128] rowwise maxima (per col-half)
    float* wsum   = smem + 256;      // [8]
    float* tiles  = smem + HDR_FLOATS;

    const int tid  = threadIdx.x;
    const int wid  = tid >> 5;
    const int lane = tid & 31;
    const int wr   = wid & 3;   // warp row  (rows wr*32 .. +31)
    const int wc   = wid >> 2;  // warp col  (cols wc*64 .. +63)
    const int qid  = lane >> 2; // 0..7
    const int qlan = lane & 3;  // 0..3

    const size_t pair = blockIdx.x;
    const float* ctx = in + pair * (size_t)(2 * L * D);

    // ---- cp.async plan: 12x 16B per thread per chunk (6 A + 6 B) ----
    // thread -> (row = tid>>1, half = tid&1); each half covers 6 consecutive
    // 16B segs (96B) of the 192B chunk-row.
    const int lrow  = tid >> 1;   // 0..127
    const int lhalf = tid & 1;    // 0..1
    const float* gbase = ctx + (size_t)lrow * D + lhalf * 24;
    const uint32_t dst0 = smem_u32(tiles) + (uint32_t)(lrow * RS + lhalf * 24) * 4u;

    // frag LDS base indices (immediate-offset loads from these)
    const int idxA = (wr * 32 + qid) * RS + qlan;
    const int idxB = (wc * 64 + qid) * RS + qlan;

    // ---- accumulators: 2 m-tiles x 8 n-tiles x 4 regs ----
    float acc[2][8][4];
#pragma unroll
    for (int mt = 0; mt < 2; mt++)
#pragma unroll
        for (int nt = 0; nt < 8; nt++)
#pragma unroll
            for (int r = 0; r < 4; r++) acc[mt][nt][r] = 0.0f;

    // issue cp.async group for chunk c into stage c%2
    auto issue = [&](int c) {
        const float* pa = gbase + c * KC;
        const uint32_t da = dst0 + (uint32_t)(c & 1) * STAGE_BYTES;
#pragma unroll
        for (int i = 0; i < 6; i++) {
            cp_async16(da + i * 16u, pa + i * 4);
            cp_async16(da + TILE_BYTES + i * 16u, pa + (size_t)L * D + i * 4);
        }
        cp_commit();
    };

    // prologue: chunk 0 in flight
    issue(0);

    uint32_t A[2][2][4];
    uint32_t Bf[2][8][2];

#pragma unroll 1
    for (int c = 0; c < NCH; c++) {
        cp_wait0();       // my stores for chunk c complete
        __syncthreads();  // everyone's chunk-c data visible; chunk c-1 reads done

        // refill the buffer chunk c-1 used (stage (c+1)%2) — safe after barrier
        if (c + 1 < NCH) issue(c + 1);

        const float* sA = tiles + (size_t)(c & 1) * STAGE_FLOATS;
        const float* pA = sA + idxA;
        const float* pB = sA + TILE_FLOATS + idxB;

        load_a(A[0], pA, 0);
        load_b(Bf[0], pB, 0);

#pragma unroll
        for (int ks = 0; ks < NKS; ks++) {
            const int cur = ks & 1, nxt = cur ^ 1;
            if (ks < NKS - 1) {
                load_a(A[nxt], pA, (ks + 1) * 8);
                load_b(Bf[nxt], pB, (ks + 1) * 8);
            }
#pragma unroll
            for (int mt = 0; mt < 2; mt++)
#pragma unroll
                for (int nt = 0; nt < 8; nt++)
                    mma_tf32(acc[mt][nt], A[cur][mt], Bf[cur][nt]);
        }
    }

    // ---- epilogue: rowwise max over this warp's 64 cols, then combine ----
    // acc reg r holds (row = base + 8*(r>>1), col = col0 + (r&1))
#pragma unroll
    for (int mt = 0; mt < 2; mt++) {
#pragma unroll
        for (int h = 0; h < 2; h++) {
            float m = __int_as_float(0xff800000);
#pragma unroll
            for (int nt = 0; nt < 8; nt++) {
                m = fmaxf(m, acc[mt][nt][2 * h]);
                m = fmaxf(m, acc[mt][nt][2 * h + 1]);
            }
            m = fmaxf(m, __shfl_xor_sync(0xffffffffu, m, 1));
            m = fmaxf(m, __shfl_xor_sync(0xffffffffu, m, 2));
            if (qlan == 0)
                rowbuf[wc * 128 + wr * 32 + mt * 16 + h * 8 + qid] = m;
        }
    }
    __syncthreads();

    if (tid < 128) {
        float v = fmaxf(rowbuf[tid], rowbuf[128 + tid]);
#pragma unroll
        for (int o = 16; o > 0; o >>= 1) v += __shfl_xor_sync(0xffffffffu, v, o);
        if (lane == 0) wsum[wid] = v;
    }
    __syncthreads();
    if (tid == 0) out[pair] = wsum[0] + wsum[1] + wsum[2] + wsum[3];
}

// ---------------- launch ----------------
extern "C" void kernel_launch(void* const* d_in, const int* in_sizes, int n_in,
                              void* d_out, int out_size) {
    const float* in = (const float*)d_in[0];
    float* out = (float*)d_out;
    const int pairs = in_sizes[0] / (2 * L * D);  // B*K = 1024

    cudaFuncSetAttribute(som_kernel, cudaFuncAttributeMaxDynamicSharedMemorySize, SMEM_DYN);
    som_kernel<<<pairs, 256, SMEM_DYN>>>(in, out);
}

// round 6
// speedup vs baseline: 1.8452x; 1.8452x over previous
#include <cuda_runtime.h>
#include <cstdint>

#define DINL __device__ __forceinline__

// ---------------- problem constants ----------------
static constexpr int L   = 128;  // rows per operand tile (M and N)
static constexpr int D   = 768;  // reduction dim
static constexpr int KC  = 32;   // fp32 elements per K-chunk
static constexpr int NCH = D / KC;  // 24 chunks
static constexpr int STAGES = 3;

// smem: padded row stride of 36 floats -> conflict-free LDS and STS patterns
static constexpr int RS = 36;                         // row stride in floats
static constexpr int TILE_FLOATS  = L * RS;           // 4608 floats = 18 KB
static constexpr int STAGE_FLOATS = 2 * TILE_FLOATS;  // A + B = 36 KB
static constexpr int HDR_FLOATS   = 288;              // rowbuf[256]+wsum[8]+mbars
static constexpr uint32_t TILE_BYTES  = TILE_FLOATS * 4;   // 18432
static constexpr uint32_t STAGE_BYTES = STAGE_FLOATS * 4;  // 36864
static constexpr uint32_t ROWBLK_BYTES = 32 * RS * 4;      // 4608
static constexpr uint32_t MBAR_OFF = 264 * 4;              // byte offset of mbarriers
static constexpr uint32_t SMEM_DYN =
    (HDR_FLOATS + STAGES * STAGE_FLOATS) * sizeof(float);  // 111,744 B

// ---------------- PTX helpers ----------------
DINL uint32_t smem_u32(const void* p) {
    uint32_t a;
    asm("{ .reg .u64 t; cvta.to.shared.u64 t, %1; cvt.u32.u64 %0, t; }" : "=r"(a) : "l"(p));
    return a;
}
DINL void cp_async16(uint32_t dst, const void* src) {
    asm volatile("cp.async.cg.shared.global [%0], [%1], 16;" :: "r"(dst), "l"(src) : "memory");
}
DINL void mbar_init(uint32_t a, uint32_t cnt) {
    asm volatile("mbarrier.init.shared.b64 [%0], %1;" :: "r"(a), "r"(cnt) : "memory");
}
DINL void mbar_arrive(uint32_t a) {
    asm volatile("mbarrier.arrive.shared.b64 _, [%0];" :: "r"(a) : "memory");
}
// arrive on mbar when all of this thread's prior cp.async have completed
DINL void cp_async_mbar_arrive(uint32_t a) {
    asm volatile("cp.async.mbarrier.arrive.noinc.shared.b64 [%0];" :: "r"(a) : "memory");
}
DINL void mbar_wait(uint32_t a, uint32_t parity) {
    asm volatile(
        "{\n\t.reg .pred P;\n"
        "WL%=:\n\t"
        "mbarrier.try_wait.parity.shared.b64 P, [%0], %1;\n\t"
        "@P bra WD%=;\n\t"
        "bra WL%=;\n"
        "WD%=:\n\t}"
        :: "r"(a), "r"(parity) : "memory");
}

DINL void mma_tf32(float* d, const uint32_t* a, const uint32_t* b) {
    asm volatile(
        "mma.sync.aligned.m16n8k8.row.col.f32.tf32.tf32.f32 "
        "{%0,%1,%2,%3}, {%4,%5,%6,%7}, {%8,%9}, {%0,%1,%2,%3};\n"
        : "+f"(d[0]), "+f"(d[1]), "+f"(d[2]), "+f"(d[3])
        : "r"(a[0]), "r"(a[1]), "r"(a[2]), "r"(a[3]), "r"(b[0]), "r"(b[1]));
}

DINL uint32_t f2u(float x) { return __float_as_uint(x); }

// A fragment for this warp's two 16-row m-tiles at k-offset k0.
DINL void load_a(uint32_t (&a)[2][4], const float* __restrict__ pA, int k0) {
#pragma unroll
    for (int mt = 0; mt < 2; mt++) {
        const int base = mt * 16 * RS;
        a[mt][0] = f2u(pA[base + k0]);
        a[mt][1] = f2u(pA[base + 8 * RS + k0]);
        a[mt][2] = f2u(pA[base + k0 + 4]);
        a[mt][3] = f2u(pA[base + 8 * RS + k0 + 4]);
    }
}
// B fragments for this warp's eight 8-col n-tiles at k-offset k0.
DINL void load_b(uint32_t (&b)[8][2], const float* __restrict__ pB, int k0) {
#pragma unroll
    for (int nt = 0; nt < 8; nt++) {
        b[nt][0] = f2u(pB[nt * 8 * RS + k0]);
        b[nt][1] = f2u(pB[nt * 8 * RS + k0 + 4]);
    }
}

// ---------------- kernel ----------------
// One CTA per (b,k) pair. sim = ctx @ ent^T via tf32 mma.sync in registers;
// out[pair] = sum over rows of rowwise max of sim.
// Pipeline synchronized purely by mbarriers (no __syncthreads in the mainloop)
// so warps can drift and anti-phase their LDS / MMA bursts.
__global__ void __launch_bounds__(256, 2)
som_kernel(const float* __restrict__ in, float* __restrict__ out) {
    extern __shared__ float smem[];
    float* rowbuf = smem;            // [2][128] rowwise maxima (per col-half)
    float* wsum   = smem + 256;      // [8]
    float* tiles  = smem + HDR_FLOATS;

    const int tid  = threadIdx.x;
    const int wid  = tid >> 5;
    const int lane = tid & 31;
    const int wr   = wid & 3;   // warp row  (rows wr*32 .. +31)
    const int wc   = wid >> 2;  // warp col  (cols wc*64 .. +63)
    const int qid  = lane >> 2; // 0..7
    const int qlan = lane & 3;  // 0..3

    const uint32_t smem_b = smem_u32(smem);
    const uint32_t mb_full = smem_b + MBAR_OFF;       // full[0..2]
    const uint32_t mb_free = smem_b + MBAR_OFF + 24;  // free[0..2]

    if (tid == 0) {
#pragma unroll
        for (int s = 0; s < STAGES; s++) {
            mbar_init(mb_full + 8u * s, 256);
            mbar_init(mb_free + 8u * s, 256);
        }
    }
    __syncthreads();

    const size_t pair = blockIdx.x;
    const float* ctx = in + pair * (size_t)(2 * L * D);

    // ---- cp.async plan: 8x 16B per thread per chunk (4 A-rows + 4 B-rows) ----
    const int lrow = tid >> 3;  // 0..31
    const int lseg = tid & 7;   // 0..7
    const float* gbase = ctx + (size_t)lrow * D + lseg * 4;
    const uint32_t dst0 = smem_u32(tiles) + (uint32_t)(lrow * RS + lseg * 4) * 4u;

    // frag LDS base indices
    const int idxA = (wr * 32 + qid) * RS + qlan;
    const int idxB = (wc * 64 + qid) * RS + qlan;

    // ---- accumulators: 2 m-tiles x 8 n-tiles x 4 regs ----
    float acc[2][8][4];
#pragma unroll
    for (int mt = 0; mt < 2; mt++)
#pragma unroll
        for (int nt = 0; nt < 8; nt++)
#pragma unroll
            for (int r = 0; r < 4; r++) acc[mt][nt][r] = 0.0f;

    // issue cp.async for chunk c into stage c%3, then arm full[s]
    auto issue = [&](int c) {
        const float* pa = gbase + c * KC;
        const uint32_t da = dst0 + (uint32_t)(c % STAGES) * STAGE_BYTES;
#pragma unroll
        for (int i = 0; i < 4; i++) {
            cp_async16(da + i * ROWBLK_BYTES, pa + (size_t)i * 32 * D);
            cp_async16(da + TILE_BYTES + i * ROWBLK_BYTES,
                       pa + (size_t)L * D + (size_t)i * 32 * D);
        }
        cp_async_mbar_arrive(mb_full + 8u * (uint32_t)(c % STAGES));
    };

    // prologue: chunks 0 and 1 in flight
    issue(0);
    issue(1);

    uint32_t A[2][2][4];
    uint32_t Bf[2][8][2];

#pragma unroll 1
    for (int c = 0; c < NCH; c++) {
        const uint32_t s = (uint32_t)(c % STAGES);
        mbar_wait(mb_full + 8u * s, (uint32_t)((c / 3) & 1));  // chunk c visible

        const float* sA = tiles + (size_t)s * STAGE_FLOATS;
        const float* pA = sA + idxA;
        const float* pB = sA + TILE_FLOATS + idxB;

        load_a(A[0], pA, 0);
        load_b(Bf[0], pB, 0);
        // prefetch ks=1 fragments
        load_a(A[1], pA, 8);
        load_b(Bf[1], pB, 8);

        // ks = 0 MMAs
#pragma unroll
        for (int mt = 0; mt < 2; mt++)
#pragma unroll
            for (int nt = 0; nt < 8; nt++)
                mma_tf32(acc[mt][nt], A[0][mt], Bf[0][nt]);

        // mid-compute pipeline refill: stage (c+2)%3 was last read at chunk c-1
        if (c + 2 < NCH) {
            if (c >= 1)
                mbar_wait(mb_free + 8u * (uint32_t)((c + 2) % STAGES),
                          (uint32_t)(((c - 1) / 3) & 1));
            issue(c + 2);
        }

        // ks = 1..3
#pragma unroll
        for (int ks = 1; ks < 4; ks++) {
            const int cur = ks & 1, nxt = cur ^ 1;
            if (ks < 3) {
                load_a(A[nxt], pA, (ks + 1) * 8);
                load_b(Bf[nxt], pB, (ks + 1) * 8);
            }
#pragma unroll
            for (int mt = 0; mt < 2; mt++)
#pragma unroll
                for (int nt = 0; nt < 8; nt++)
                    mma_tf32(acc[mt][nt], A[cur][mt], Bf[cur][nt]);
        }

        // done reading stage s (release orders the LDS reads above)
        mbar_arrive(mb_free + 8u * s);
    }

    // ---- epilogue: rowwise max over this warp's 64 cols, then combine ----
#pragma unroll
    for (int mt = 0; mt < 2; mt++) {
#pragma unroll
        for (int h = 0; h < 2; h++) {
            float m = __int_as_float(0xff800000);
#pragma unroll
            for (int nt = 0; nt < 8; nt++) {
                m = fmaxf(m, acc[mt][nt][2 * h]);
                m = fmaxf(m, acc[mt][nt][2 * h + 1]);
            }
            m = fmaxf(m, __shfl_xor_sync(0xffffffffu, m, 1));
            m = fmaxf(m, __shfl_xor_sync(0xffffffffu, m, 2));
            if (qlan == 0)
                rowbuf[wc * 128 + wr * 32 + mt * 16 + h * 8 + qid] = m;
        }
    }
    __syncthreads();

    if (tid < 128) {
        float v = fmaxf(rowbuf[tid], rowbuf[128 + tid]);
#pragma unroll
        for (int o = 16; o > 0; o >>= 1) v += __shfl_xor_sync(0xffffffffu, v, o);
        if (lane == 0) wsum[wid] = v;
    }
    __syncthreads();
    if (tid == 0) out[pair] = wsum[0] + wsum[1] + wsum[2] + wsum[3];
}

// ---------------- launch ----------------
extern "C" void kernel_launch(void* const* d_in, const int* in_sizes, int n_in,
                              void* d_out, int out_size) {
    const float* in = (const float*)d_in[0];
    float* out = (float*)d_out;
    const int pairs = in_sizes[0] / (2 * L * D);  // B*K = 1024

    cudaFuncSetAttribute(som_kernel, cudaFuncAttributeMaxDynamicSharedMemorySize, SMEM_DYN);
    som_kernel<<<pairs, 256, SMEM_DYN>>>(in, out);
}

// round 7
// speedup vs baseline: 1.9226x; 1.0420x over previous
#include <cuda_runtime.h>
#include <cstdint>

#define DINL __device__ __forceinline__

// ---------------- problem constants ----------------
static constexpr int L   = 128;  // rows per operand tile (M and N)
static constexpr int D   = 768;  // reduction dim
static constexpr int KC  = 32;   // fp32 elements per K-chunk
static constexpr int NCH = D / KC;  // 24 chunks
static constexpr int STAGES = 3;
static constexpr int NTHR = 128; // 4 warps, 2x2 grid of 64x64 warp tiles

// smem: padded row stride of 36 floats -> conflict-free LDS and STS patterns
static constexpr int RS = 36;                         // row stride in floats
static constexpr int TILE_FLOATS  = L * RS;           // 4608 floats = 18 KB
static constexpr int STAGE_FLOATS = 2 * TILE_FLOATS;  // A + B = 36 KB
static constexpr int HDR_FLOATS   = 288;              // rowbuf[256]+wsum[8]+mbars
static constexpr uint32_t TILE_BYTES  = TILE_FLOATS * 4;   // 18432
static constexpr uint32_t STAGE_BYTES = STAGE_FLOATS * 4;  // 36864
static constexpr uint32_t ROWBLK_BYTES = 16 * RS * 4;      // 2304 (16-row block)
static constexpr uint32_t MBAR_OFF = 264 * 4;              // byte offset of mbarriers
static constexpr uint32_t SMEM_DYN =
    (HDR_FLOATS + STAGES * STAGE_FLOATS) * sizeof(float);  // 111,744 B

// ---------------- PTX helpers ----------------
DINL uint32_t smem_u32(const void* p) {
    uint32_t a;
    asm("{ .reg .u64 t; cvta.to.shared.u64 t, %1; cvt.u32.u64 %0, t; }" : "=r"(a) : "l"(p));
    return a;
}
DINL void cp_async16(uint32_t dst, const void* src) {
    asm volatile("cp.async.cg.shared.global [%0], [%1], 16;" :: "r"(dst), "l"(src) : "memory");
}
DINL void mbar_init(uint32_t a, uint32_t cnt) {
    asm volatile("mbarrier.init.shared.b64 [%0], %1;" :: "r"(a), "r"(cnt) : "memory");
}
DINL void mbar_arrive(uint32_t a) {
    asm volatile("mbarrier.arrive.shared.b64 _, [%0];" :: "r"(a) : "memory");
}
// arrive on mbar when all of this thread's prior cp.async have completed
DINL void cp_async_mbar_arrive(uint32_t a) {
    asm volatile("cp.async.mbarrier.arrive.noinc.shared.b64 [%0];" :: "r"(a) : "memory");
}
DINL void mbar_wait(uint32_t a, uint32_t parity) {
    asm volatile(
        "{\n\t.reg .pred P;\n"
        "WL%=:\n\t"
        "mbarrier.try_wait.parity.shared.b64 P, [%0], %1;\n\t"
        "@P bra WD%=;\n\t"
        "bra WL%=;\n"
        "WD%=:\n\t}"
        :: "r"(a), "r"(parity) : "memory");
}

DINL void mma_tf32(float* d, const uint32_t* a, const uint32_t* b) {
    asm volatile(
        "mma.sync.aligned.m16n8k8.row.col.f32.tf32.tf32.f32 "
        "{%0,%1,%2,%3}, {%4,%5,%6,%7}, {%8,%9}, {%0,%1,%2,%3};\n"
        : "+f"(d[0]), "+f"(d[1]), "+f"(d[2]), "+f"(d[3])
        : "r"(a[0]), "r"(a[1]), "r"(a[2]), "r"(a[3]), "r"(b[0]), "r"(b[1]));
}

DINL uint32_t f2u(float x) { return __float_as_uint(x); }

// A fragments: four 16-row m-tiles at k-offset k0. pA = sA + (wr*64+qid)*RS + qlan.
DINL void load_a(uint32_t (&a)[4][4], const float* __restrict__ pA, int k0) {
#pragma unroll
    for (int mt = 0; mt < 4; mt++) {
        const int base = mt * 16 * RS;
        a[mt][0] = f2u(pA[base + k0]);
        a[mt][1] = f2u(pA[base + 8 * RS + k0]);
        a[mt][2] = f2u(pA[base + k0 + 4]);
        a[mt][3] = f2u(pA[base + 8 * RS + k0 + 4]);
    }
}
// B fragments: eight 8-col n-tiles at k-offset k0. pB = sB + (wc*64+qid)*RS + qlan.
DINL void load_b(uint32_t (&b)[8][2], const float* __restrict__ pB, int k0) {
#pragma unroll
    for (int nt = 0; nt < 8; nt++) {
        b[nt][0] = f2u(pB[nt * 8 * RS + k0]);
        b[nt][1] = f2u(pB[nt * 8 * RS + k0 + 4]);
    }
}

// ---------------- kernel ----------------
// One CTA (128 threads) per (b,k) pair. sim = ctx @ ent^T via tf32 mma.sync;
// out[pair] = sum over rows of rowwise max of sim.
// 2x2 warp grid of 64x64 tiles -> fragment smem traffic (2+2)x16KB per chunk
// (vs (4+2) with 8 warps). mbarrier pipeline, no __syncthreads in mainloop.
__global__ void __launch_bounds__(NTHR, 2)
som_kernel(const float* __restrict__ in, float* __restrict__ out) {
    extern __shared__ float smem[];
    float* rowbuf = smem;            // [2][128] rowwise maxima (per col-half)
    float* wsum   = smem + 256;      // [4]
    float* tiles  = smem + HDR_FLOATS;

    const int tid  = threadIdx.x;
    const int wid  = tid >> 5;
    const int lane = tid & 31;
    const int wr   = wid >> 1;  // warp row  (rows wr*64 .. +63)
    const int wc   = wid & 1;   // warp col  (cols wc*64 .. +63)
    const int qid  = lane >> 2; // 0..7
    const int qlan = lane & 3;  // 0..3

    const uint32_t smem_b = smem_u32(smem);
    const uint32_t mb_full = smem_b + MBAR_OFF;       // full[0..2]
    const uint32_t mb_free = smem_b + MBAR_OFF + 24;  // free[0..2]

    if (tid == 0) {
#pragma unroll
        for (int s = 0; s < STAGES; s++) {
            mbar_init(mb_full + 8u * s, NTHR);
            mbar_init(mb_free + 8u * s, NTHR);
        }
    }
    __syncthreads();

    const size_t pair = blockIdx.x;
    const float* ctx = in + pair * (size_t)(2 * L * D);

    // ---- cp.async plan: 16x 16B per thread per chunk (8 A-rows + 8 B-rows) ----
    // thread -> (row16 = tid>>3 in 0..15, seg = tid&7); covers rows row16+16*i.
    const int lrow = tid >> 3;  // 0..15
    const int lseg = tid & 7;   // 0..7
    const float* gbase = ctx + (size_t)lrow * D + lseg * 4;
    const uint32_t dst0 = smem_u32(tiles) + (uint32_t)(lrow * RS + lseg * 4) * 4u;

    // frag LDS base indices
    const int idxA = (wr * 64 + qid) * RS + qlan;
    const int idxB = (wc * 64 + qid) * RS + qlan;

    // ---- accumulators: 4 m-tiles x 8 n-tiles x 4 regs ----
    float acc[4][8][4];
#pragma unroll
    for (int mt = 0; mt < 4; mt++)
#pragma unroll
        for (int nt = 0; nt < 8; nt++)
#pragma unroll
            for (int r = 0; r < 4; r++) acc[mt][nt][r] = 0.0f;

    // issue cp.async for chunk c into stage c%3, then arm full[s]
    auto issue = [&](int c) {
        const float* pa = gbase + c * KC;
        const uint32_t da = dst0 + (uint32_t)(c % STAGES) * STAGE_BYTES;
#pragma unroll
        for (int i = 0; i < 8; i++) {
            cp_async16(da + i * ROWBLK_BYTES, pa + (size_t)i * 16 * D);
            cp_async16(da + TILE_BYTES + i * ROWBLK_BYTES,
                       pa + (size_t)L * D + (size_t)i * 16 * D);
        }
        cp_async_mbar_arrive(mb_full + 8u * (uint32_t)(c % STAGES));
    };

    // prologue: chunks 0 and 1 in flight
    issue(0);
    issue(1);

    uint32_t A[2][4][4];
    uint32_t Bf[2][8][2];

#pragma unroll 1
    for (int c = 0; c < NCH; c++) {
        const uint32_t s = (uint32_t)(c % STAGES);
        mbar_wait(mb_full + 8u * s, (uint32_t)((c / 3) & 1));  // chunk c visible

        const float* sA = tiles + (size_t)s * STAGE_FLOATS;
        const float* pA = sA + idxA;
        const float* pB = sA + TILE_FLOATS + idxB;

        load_a(A[0], pA, 0);
        load_b(Bf[0], pB, 0);
        // prefetch ks=1 fragments
        load_a(A[1], pA, 8);
        load_b(Bf[1], pB, 8);

        // ks = 0 MMAs
#pragma unroll
        for (int mt = 0; mt < 4; mt++)
#pragma unroll
            for (int nt = 0; nt < 8; nt++)
                mma_tf32(acc[mt][nt], A[0][mt], Bf[0][nt]);

        // mid-compute pipeline refill: stage (c+2)%3 was last read at chunk c-1
        if (c + 2 < NCH) {
            if (c >= 1)
                mbar_wait(mb_free + 8u * (uint32_t)((c + 2) % STAGES),
                          (uint32_t)(((c - 1) / 3) & 1));
            issue(c + 2);
        }

        // ks = 1..3
#pragma unroll
        for (int ks = 1; ks < 4; ks++) {
            const int cur = ks & 1, nxt = cur ^ 1;
            if (ks < 3) {
                load_a(A[nxt], pA, (ks + 1) * 8);
                load_b(Bf[nxt], pB, (ks + 1) * 8);
            }
#pragma unroll
            for (int mt = 0; mt < 4; mt++)
#pragma unroll
                for (int nt = 0; nt < 8; nt++)
                    mma_tf32(acc[mt][nt], A[cur][mt], Bf[cur][nt]);
        }

        // done reading stage s (release orders the LDS reads above)
        mbar_arrive(mb_free + 8u * s);
    }

    // ---- epilogue: rowwise max over this warp's 64 cols, then combine ----
    // acc reg r holds (row = wr*64 + mt*16 + 8*(r>>1) + qid, col = n0 + 2*qlan + (r&1))
#pragma unroll
    for (int mt = 0; mt < 4; mt++) {
#pragma unroll
        for (int h = 0; h < 2; h++) {
            float m = __int_as_float(0xff800000);
#pragma unroll
            for (int nt = 0; nt < 8; nt++) {
                m = fmaxf(m, acc[mt][nt][2 * h]);
                m = fmaxf(m, acc[mt][nt][2 * h + 1]);
            }
            m = fmaxf(m, __shfl_xor_sync(0xffffffffu, m, 1));
            m = fmaxf(m, __shfl_xor_sync(0xffffffffu, m, 2));
            if (qlan == 0)
                rowbuf[wc * 128 + wr * 64 + mt * 16 + h * 8 + qid] = m;
        }
    }
    __syncthreads();

    {
        float v = fmaxf(rowbuf[tid], rowbuf[128 + tid]);
#pragma unroll
        for (int o = 16; o > 0; o >>= 1) v += __shfl_xor_sync(0xffffffffu, v, o);
        if (lane == 0) wsum[wid] = v;
    }
    __syncthreads();
    if (tid == 0) out[pair] = wsum[0] + wsum[1] + wsum[2] + wsum[3];
}

// ---------------- launch ----------------
extern "C" void kernel_launch(void* const* d_in, const int* in_sizes, int n_in,
                              void* d_out, int out_size) {
    const float* in = (const float*)d_in[0];
    float* out = (float*)d_out;
    const int pairs = in_sizes[0] / (2 * L * D);  // B*K = 1024

    cudaFuncSetAttribute(som_kernel, cudaFuncAttributeMaxDynamicSharedMemorySize, SMEM_DYN);
    som_kernel<<<pairs, NTHR, SMEM_DYN>>>(in, out);
}